// round 15
// baseline (speedup 1.0000x reference)
#include <cuda_runtime.h>
#include <cuda_fp16.h>
#include <cstdint>

#define NN 100000
#define EE 1600000
#define NSB 98            // ceil(NN/1024)
#define PG 304            // persistent GEMM grid (2 x 152 SMs)
#define PP 608            // persistent prep grid (4 x 152 SMs, all resident)
#define GT (PP * 256)
typedef unsigned long long u64;
typedef unsigned int u32;

// ---------------- device scratch ----------------
__device__ __half g_f16[(size_t)NN * 128];    // feat fp16 (pre-scaled by dno)
__device__ __half g_a16[(size_t)NN * 256];    // agg output fp16
__device__ __half g_hh[(size_t)NN * 256];     // L1 out fp16 (pre-scaled by dno)
__device__ __half g_p16[(size_t)NN * 256];    // L2 out fp16 (unscaled)
__device__ __half g_q16[(size_t)NN * 128];    // L3 gemm out fp16 (pre-scaled by dno)
__device__ __half g_w1[256 * 128];
__device__ __half g_w2[256 * 256];
__device__ __half g_w3[128 * 256];
__device__ float g_dno[NN], g_dni[NN];
__device__ int g_cout[NN], g_cin[NN];
__device__ int g_ptr[NN + 1], g_cur[NN], g_csrc[EE];
__device__ int g_part[128];
__device__ u32 g_bc[4];   // grid-barrier counters (zero-init; self-resetting)

// ---------------- helpers ----------------
__device__ __forceinline__ void addh8(float* a, const uint4 v) {
    const __half2* h = (const __half2*)&v;
    #pragma unroll
    for (int j = 0; j < 4; j++) {
        float2 f = __half22float2(h[j]);
        a[2 * j] += f.x; a[2 * j + 1] += f.y;
    }
}
__device__ __forceinline__ uint4 pk8(const float* a) {
    __half2 h0 = __floats2half2_rn(a[0], a[1]);
    __half2 h1 = __floats2half2_rn(a[2], a[3]);
    __half2 h2 = __floats2half2_rn(a[4], a[5]);
    __half2 h3 = __floats2half2_rn(a[6], a[7]);
    return make_uint4(*(u32*)&h0, *(u32*)&h1, *(u32*)&h2, *(u32*)&h3);
}
__device__ __forceinline__ void mma16816(float* c, const u32* a, const u32* b) {
    asm volatile(
        "mma.sync.aligned.m16n8k16.row.col.f32.f16.f16.f32 "
        "{%0,%1,%2,%3},{%4,%5,%6,%7},{%8,%9},{%0,%1,%2,%3};"
        : "+f"(c[0]), "+f"(c[1]), "+f"(c[2]), "+f"(c[3])
        : "r"(a[0]), "r"(a[1]), "r"(a[2]), "r"(a[3]), "r"(b[0]), "r"(b[1]));
}
__device__ __forceinline__ void cpa16(void* s, const void* g) {
    u32 sa = (u32)__cvta_generic_to_shared(s);
    asm volatile("cp.async.cg.shared.global [%0], [%1], 16;" :: "r"(sa), "l"(g));
}
__device__ __forceinline__ void ldsm4(u32* r, u32 a) {
    asm volatile("ldmatrix.sync.aligned.m8n8.x4.shared.b16 {%0,%1,%2,%3},[%4];"
                 : "=r"(r[0]), "=r"(r[1]), "=r"(r[2]), "=r"(r[3]) : "r"(a));
}

// grid barrier: all PP CTAs resident by construction. Last arriver at idx
// resets counter 'prev' (all CTAs provably past it). Counter 3 cleared at
// kernel start for replay safety.
__device__ __forceinline__ void gbar(int idx, int prev) {
    __syncthreads();
    if (threadIdx.x == 0) {
        __threadfence();
        u32 v = atomicAdd(&g_bc[idx], 1);
        if (v == PP - 1 && prev >= 0) g_bc[prev] = 0;
        while (*(volatile u32*)&g_bc[idx] < PP) { }
        __threadfence();
    }
    __syncthreads();
}

// ---------------- fused persistent prep: zero|deg+wtr|norm+part|scat|fill+cvt ---
__global__ void __launch_bounds__(256, 4)
k_prep(const int* __restrict__ src, const int* __restrict__ dst,
       const float* __restrict__ W1, const float* __restrict__ W2,
       const float* __restrict__ W3, const float* __restrict__ feat) {
    __shared__ int ws[32];
    __shared__ int sbase;
    const int bx = blockIdx.x, tid = threadIdx.x;
    const int lane = tid & 31, w = tid >> 5;
    const int gt = bx * 256 + tid;

    if (gt == 0) g_bc[3] = 0;   // clear leftover counter from previous replay

    // ---- phase 0: zero degree arrays ----
    if (gt < (NN + 3) / 4) {
        ((int4*)g_cout)[gt] = make_int4(0, 0, 0, 0);
        ((int4*)g_cin)[gt] = make_int4(0, 0, 0, 0);
    }
    gbar(0, -1);

    // ---- phase 1: degree atomics + weight transposes ----
    for (int i = gt; i < EE; i += GT) {
        atomicAdd(&g_cout[__ldg(&src[i])], 1);
        atomicAdd(&g_cin[__ldg(&dst[i])], 1);
    }
    for (int i = gt; i < 131072; i += GT) {
        if (i < 32768) {
            int n = i / 128, k = i % 128;
            g_w1[i] = __float2half_rn(W1[(size_t)k * 256 + n]);
        } else if (i < 98304) {
            int j = i - 32768;
            int n = j / 256, k = j % 256;
            g_w2[j] = __float2half_rn(W2[(size_t)k * 256 + n]);
        } else {
            int j = i - 98304;
            int n = j / 256, k = j % 256;
            g_w3[j] = __float2half_rn(W3[(size_t)k * 128 + n]);
        }
    }
    gbar(1, 0);

    // ---- phase 2: degree norms + per-segment partial sums ----
    for (int i = gt; i < NN; i += GT) {
        int co = __ldcg(&g_cout[i]); if (co < 1) co = 1;
        int ci = __ldcg(&g_cin[i]);  if (ci < 1) ci = 1;
        g_dno[i] = rsqrtf((float)co);
        g_dni[i] = rsqrtf((float)ci);
    }
    if (bx < NSB) {
        int s = 0;
        for (int j = tid; j < 1024; j += 256) {
            int i = bx * 1024 + j;
            s += (i < NN) ? __ldcg(&g_cin[i]) : 0;
        }
        #pragma unroll
        for (int o = 16; o; o >>= 1) s += __shfl_xor_sync(0xffffffffu, s, o);
        if (lane == 0) ws[w] = s;
        __syncthreads();
        if (tid == 0) {
            int t = 0;
            #pragma unroll
            for (int j = 0; j < 8; j++) t += ws[j];
            g_part[bx] = t;
        }
    }
    gbar(2, 1);

    // ---- phase 3: CSR pointer scatter (prefix), 4 elems/thread ----
    if (bx < NSB) {
        // base = sum g_part[0..bx-1]
        int pv = (tid < bx) ? __ldcg(&g_part[tid]) : 0;
        #pragma unroll
        for (int o = 16; o; o >>= 1) pv += __shfl_xor_sync(0xffffffffu, pv, o);
        if (lane == 0) ws[w] = pv;
        __syncthreads();
        if (tid == 0) {
            int t = 0;
            #pragma unroll
            for (int j = 0; j < 8; j++) t += ws[j];
            sbase = t;
        }
        __syncthreads();

        const int i0 = bx * 1024 + tid * 4;
        int v0 = (i0 + 0 < NN) ? __ldcg(&g_cin[i0 + 0]) : 0;
        int v1 = (i0 + 1 < NN) ? __ldcg(&g_cin[i0 + 1]) : 0;
        int v2 = (i0 + 2 < NN) ? __ldcg(&g_cin[i0 + 2]) : 0;
        int v3 = (i0 + 3 < NN) ? __ldcg(&g_cin[i0 + 3]) : 0;
        int ts = v0 + v1 + v2 + v3;
        int x = ts;
        #pragma unroll
        for (int o = 1; o < 32; o <<= 1) {
            int t = __shfl_up_sync(0xffffffffu, x, o);
            if (lane >= o) x += t;
        }
        __syncthreads();   // ws reuse safety
        if (lane == 31) ws[w] = x;
        __syncthreads();
        if (w == 0) {
            int s2 = (lane < 8) ? ws[lane] : 0;
            #pragma unroll
            for (int o = 1; o < 32; o <<= 1) {
                int t = __shfl_up_sync(0xffffffffu, s2, o);
                if (lane >= o) s2 += t;
            }
            if (lane < 8) ws[lane] = s2;
        }
        __syncthreads();
        int pre = (w > 0) ? ws[w - 1] : 0;
        int e0 = sbase + pre + x - ts;
        int e1 = e0 + v0, e2 = e1 + v1, e3 = e2 + v2;
        if (i0 + 0 < NN) { g_ptr[i0 + 0] = e0; g_cur[i0 + 0] = e0; }
        if (i0 + 1 < NN) { g_ptr[i0 + 1] = e1; g_cur[i0 + 1] = e1; }
        if (i0 + 2 < NN) { g_ptr[i0 + 2] = e2; g_cur[i0 + 2] = e2; }
        if (i0 + 3 < NN) { g_ptr[i0 + 3] = e3; g_cur[i0 + 3] = e3; }
    }
    if (gt == 0) g_ptr[NN] = EE;
    gbar(3, 2);

    // ---- phase 4: CSR fill + feat cvt * dno ----
    for (int i = gt; i < EE; i += GT) {
        int d = __ldg(&dst[i]);
        int p = atomicAdd(&g_cur[d], 1);
        g_csrc[p] = __ldg(&src[i]);
    }
    for (int i = gt; i < NN * 32; i += GT) {
        float4 v = ((const float4*)feat)[i];
        float d = __ldcg(&g_dno[i >> 5]);
        __half2 a = __floats2half2_rn(v.x * d, v.y * d);
        __half2 bb = __floats2half2_rn(v.z * d, v.w * d);
        ((uint2*)g_f16)[i] = make_uint2(*(u32*)&a, *(u32*)&bb);
    }
}

// ---------------- aggregation (warp-per-node, CSR, uint4 gathers) ----------------
template<int D, int MODE>
__global__ void k_agg(const __half* __restrict__ in,
                      __half* __restrict__ oh, float* __restrict__ of,
                      const float* __restrict__ b3) {
    const int w = (blockIdx.x << 3) + (threadIdx.x >> 5);
    const int lane = threadIdx.x & 31;
    if (w >= NN) return;
    const int beg = g_ptr[w], end = g_ptr[w + 1];
    float a[8] = {0.f, 0.f, 0.f, 0.f, 0.f, 0.f, 0.f, 0.f};

    if (D == 256) {
        int e = beg;
        for (; e + 4 <= end; e += 4) {
            int s0 = g_csrc[e], s1 = g_csrc[e + 1];
            int s2 = g_csrc[e + 2], s3 = g_csrc[e + 3];
            uint4 v0 = ((const uint4*)(in + (size_t)s0 * 256))[lane];
            uint4 v1 = ((const uint4*)(in + (size_t)s1 * 256))[lane];
            uint4 v2 = ((const uint4*)(in + (size_t)s2 * 256))[lane];
            uint4 v3 = ((const uint4*)(in + (size_t)s3 * 256))[lane];
            addh8(a, v0); addh8(a, v1); addh8(a, v2); addh8(a, v3);
        }
        for (; e < end; e++) {
            uint4 v = ((const uint4*)(in + (size_t)g_csrc[e] * 256))[lane];
            addh8(a, v);
        }
        ((uint4*)(oh + (size_t)w * 256))[lane] = pk8(a);
    } else {
        const int slot = lane >> 4;      // which edge of the pair
        const int ch = lane & 15;        // 16B chunk within row
        int e = beg;
        for (; e + 4 <= end; e += 4) {
            int e0 = g_csrc[e + slot], e1 = g_csrc[e + 2 + slot];
            uint4 v0 = ((const uint4*)(in + (size_t)e0 * 128))[ch];
            uint4 v1 = ((const uint4*)(in + (size_t)e1 * 128))[ch];
            addh8(a, v0); addh8(a, v1);
        }
        for (; e < end; e += 2) {
            int ee = e + slot;
            if (ee < end) {
                uint4 v = ((const uint4*)(in + (size_t)g_csrc[ee] * 128))[ch];
                addh8(a, v);
            }
        }
        #pragma unroll
        for (int j = 0; j < 8; j++)
            a[j] += __shfl_xor_sync(0xffffffffu, a[j], 16);
        if (MODE == 1) {
            if (slot == 0)
                ((uint4*)(oh + (size_t)w * 128))[ch] = pk8(a);
        } else {
            if (slot == 0) {
                float4 b0 = ((const float4*)b3)[2 * ch];
                float4 b1 = ((const float4*)b3)[2 * ch + 1];
                float d = g_dni[w];
                float4 o0, o1;
                o0.x = (a[0] + b0.x) * d; o0.y = (a[1] + b0.y) * d;
                o0.z = (a[2] + b0.z) * d; o0.w = (a[3] + b0.w) * d;
                o1.x = (a[4] + b1.x) * d; o1.y = (a[5] + b1.y) * d;
                o1.z = (a[6] + b1.z) * d; o1.w = (a[7] + b1.w) * d;
                ((float4*)(of + (size_t)w * 128))[2 * ch] = o0;
                ((float4*)(of + (size_t)w * 128))[2 * ch + 1] = o1;
            }
        }
    }
}

// ---------------- persistent fp16 GEMM, 4-stage pipeline, 1 sync/iter -----------
// B fragments via paired ldsm4. EPI 0: raw ; 1: bias,deg_in,LN,PReLU. SCO: *dno.
template<int K, int BM, int N, int EPI, int SCO>
__global__ void __launch_bounds__(256, 2)
k_pgemm(const __half* __restrict__ A, const __half* __restrict__ B,
        const float* __restrict__ bias, const float* __restrict__ gam,
        const float* __restrict__ bet, const float* __restrict__ alp,
        __half* __restrict__ Co, int NT) {
    extern __shared__ char smem[];
    constexpr int NW = N / 64;
    constexpr int SA = 80;
    constexpr int STG = SA * (BM + N);
    constexpr int OA = 0;
    constexpr int OB = BM * SA;
    constexpr int NIT = K / 32;
    constexpr int NS = 4;
    constexpr int POFF = NS * STG;
    float* pbias = (float*)(smem + POFF);
    float* pgam  = pbias + N;
    float* pbet  = pgam + N;
    float* red   = pbet + N;          // [BM][NW][2]

    const int tid = threadIdx.x;
    const int wid = tid >> 5, lane = tid & 31;
    const int g = lane >> 2, ti = lane & 3;
    const int mw = wid / NW, nw = wid % NW;
    const int bx = blockIdx.x, G = gridDim.x;
    const u32 smem_u = (u32)__cvta_generic_to_shared(smem);

    const u32 rA = (u32)(((lane & 7) + 8 * ((lane >> 3) & 1)) * SA + 16 * ((lane >> 4) & 1));
    const u32 rB4 = (u32)((((lane >> 4) & 1) * 8 + (lane & 7)) * SA + ((lane >> 3) & 1) * 16);

    if (EPI >= 1) {
        for (int i = tid; i < N; i += 256) {
            pbias[i] = bias[i]; pgam[i] = gam[i]; pbet[i] = bet[i];
        }
    }
    const float alpha = (EPI >= 1) ? __ldg(alp) : 0.f;

    if (bx >= NT) return;
    const int J = (NT - 1 - bx) / G + 1;
    const int total = J * NIT;

    auto issue = [&](int s) {
        const int tile = bx + (s / NIT) * G;
        const int mb = tile * BM;
        const int kb = (s % NIT) * 32;
        char* base = smem + (s % NS) * STG;
        #pragma unroll
        for (int i = tid; i < BM * 4; i += 256) {
            int r = i >> 2, q = i & 3;
            int rg = mb + r; if (rg > NN - 1) rg = NN - 1;
            cpa16(base + OA + r * SA + q * 16, A + (size_t)rg * K + kb + q * 8);
        }
        #pragma unroll
        for (int i = tid; i < N * 4; i += 256) {
            int r = i >> 2, q = i & 3;
            cpa16(base + OB + r * SA + q * 16, B + (size_t)r * K + kb + q * 8);
        }
        asm volatile("cp.async.commit_group;" ::: "memory");
    };

    float acc[2][8][4];
    #pragma unroll
    for (int t = 0; t < 2; t++)
        #pragma unroll
        for (int j = 0; j < 8; j++)
            #pragma unroll
            for (int q = 0; q < 4; q++) acc[t][j][q] = 0.f;

    issue(0);
    if (total > 1) issue(1);

    for (int s = 0; s < total; s++) {
        if (s + 2 < total) {
            issue(s + 2);
            asm volatile("cp.async.wait_group 2;" ::: "memory");
        } else if (s + 1 < total) {
            asm volatile("cp.async.wait_group 1;" ::: "memory");
        } else {
            asm volatile("cp.async.wait_group 0;" ::: "memory");
        }
        __syncthreads();   // single barrier per iteration (4-stage ring is drift-safe)
        const int buf = s % NS;
        const u32 aA = smem_u + buf * STG + OA + (u32)((mw * 32) * SA) + rA;
        const u32 aB = smem_u + buf * STG + OB + (u32)((nw * 64) * SA) + rB4;
        #pragma unroll
        for (int kt = 0; kt < 2; kt++) {
            const u32 kof = kt * 32;
            u32 af[2][4];
            #pragma unroll
            for (int t = 0; t < 2; t++) ldsm4(af[t], aA + (u32)(t * 16 * SA) + kof);
            #pragma unroll
            for (int j2 = 0; j2 < 4; j2++) {
                u32 bf[4];
                ldsm4(bf, aB + (u32)(j2 * 16 * SA) + kof);
                #pragma unroll
                for (int t = 0; t < 2; t++) {
                    mma16816(acc[t][2 * j2 + 0], af[t], bf + 0);
                    mma16816(acc[t][2 * j2 + 1], af[t], bf + 2);
                }
            }
        }

        if ((s % NIT) != NIT - 1) continue;

        // ---- epilogue for tile s/NIT ----
        const int mbase = (bx + (s / NIT) * G) * BM;
        if (EPI == 0) {
            #pragma unroll
            for (int t = 0; t < 2; t++) {
                int rl = mbase + mw * 32 + t * 16 + g;
                int rh = rl + 8;
                float sl = SCO ? g_dno[(rl < NN) ? rl : (NN - 1)] : 1.f;
                float sh = SCO ? g_dno[(rh < NN) ? rh : (NN - 1)] : 1.f;
                #pragma unroll
                for (int j = 0; j < 8; j++) {
                    int c = nw * 64 + j * 8 + ti * 2;
                    if (rl < NN) {
                        __half2 v = __floats2half2_rn(acc[t][j][0] * sl, acc[t][j][1] * sl);
                        *(__half2*)(Co + (size_t)rl * N + c) = v;
                    }
                    if (rh < NN) {
                        __half2 v = __floats2half2_rn(acc[t][j][2] * sh, acc[t][j][3] * sh);
                        *(__half2*)(Co + (size_t)rh * N + c) = v;
                    }
                }
            }
        } else {
            float mul[2], invl[2], muh[2], invh[2];
            #pragma unroll
            for (int t = 0; t < 2; t++) {
                int rloc = mw * 32 + t * 16 + g;
                int rl = mbase + rloc, rh = rl + 8;
                float dl = g_dni[(rl < NN) ? rl : (NN - 1)];
                float dh = g_dni[(rh < NN) ? rh : (NN - 1)];
                float s0 = 0.f, q0 = 0.f, s1 = 0.f, q1 = 0.f;
                #pragma unroll
                for (int j = 0; j < 8; j++) {
                    int c = nw * 64 + j * 8 + ti * 2;
                    float b0 = pbias[c], b1 = pbias[c + 1];
                    float v0 = (acc[t][j][0] + b0) * dl;
                    float v1 = (acc[t][j][1] + b1) * dl;
                    float v2 = (acc[t][j][2] + b0) * dh;
                    float v3 = (acc[t][j][3] + b1) * dh;
                    acc[t][j][0] = v0; acc[t][j][1] = v1;
                    acc[t][j][2] = v2; acc[t][j][3] = v3;
                    s0 += v0 + v1; q0 += v0 * v0 + v1 * v1;
                    s1 += v2 + v3; q1 += v2 * v2 + v3 * v3;
                }
                #pragma unroll
                for (int o = 1; o <= 2; o <<= 1) {
                    s0 += __shfl_xor_sync(0xffffffffu, s0, o);
                    q0 += __shfl_xor_sync(0xffffffffu, q0, o);
                    s1 += __shfl_xor_sync(0xffffffffu, s1, o);
                    q1 += __shfl_xor_sync(0xffffffffu, q1, o);
                }
                if (ti == 0) {
                    red[(rloc * NW + nw) * 2 + 0] = s0;
                    red[(rloc * NW + nw) * 2 + 1] = q0;
                    red[((rloc + 8) * NW + nw) * 2 + 0] = s1;
                    red[((rloc + 8) * NW + nw) * 2 + 1] = q1;
                }
            }
            __syncthreads();
            #pragma unroll
            for (int t = 0; t < 2; t++) {
                int rloc = mw * 32 + t * 16 + g;
                float s0 = 0.f, q0 = 0.f, s1 = 0.f, q1 = 0.f;
                #pragma unroll
                for (int k = 0; k < NW; k++) {
                    s0 += red[(rloc * NW + k) * 2 + 0];
                    q0 += red[(rloc * NW + k) * 2 + 1];
                    s1 += red[((rloc + 8) * NW + k) * 2 + 0];
                    q1 += red[((rloc + 8) * NW + k) * 2 + 1];
                }
                float m0 = s0 * (1.0f / N), m1 = s1 * (1.0f / N);
                mul[t] = m0; muh[t] = m1;
                invl[t] = rsqrtf(q0 * (1.0f / N) - m0 * m0 + 1e-5f);
                invh[t] = rsqrtf(q1 * (1.0f / N) - m1 * m1 + 1e-5f);
            }
            #pragma unroll
            for (int t = 0; t < 2; t++) {
                int rl = mbase + mw * 32 + t * 16 + g;
                int rh = rl + 8;
                float sl = SCO ? g_dno[(rl < NN) ? rl : (NN - 1)] : 1.f;
                float sh = SCO ? g_dno[(rh < NN) ? rh : (NN - 1)] : 1.f;
                #pragma unroll
                for (int j = 0; j < 8; j++) {
                    int c = nw * 64 + j * 8 + ti * 2;
                    float g0 = pgam[c], g1 = pgam[c + 1];
                    float e0 = pbet[c], e1 = pbet[c + 1];
                    float y0 = g0 * (acc[t][j][0] - mul[t]) * invl[t] + e0;
                    float y1 = g1 * (acc[t][j][1] - mul[t]) * invl[t] + e1;
                    float y2 = g0 * (acc[t][j][2] - muh[t]) * invh[t] + e0;
                    float y3 = g1 * (acc[t][j][3] - muh[t]) * invh[t] + e1;
                    y0 = (y0 >= 0.f) ? y0 : alpha * y0;
                    y1 = (y1 >= 0.f) ? y1 : alpha * y1;
                    y2 = (y2 >= 0.f) ? y2 : alpha * y2;
                    y3 = (y3 >= 0.f) ? y3 : alpha * y3;
                    if (SCO) { y0 *= sl; y1 *= sl; y2 *= sh; y3 *= sh; }
                    if (rl < NN)
                        *(__half2*)(Co + (size_t)rl * N + c) = __floats2half2_rn(y0, y1);
                    if (rh < NN)
                        *(__half2*)(Co + (size_t)rh * N + c) = __floats2half2_rn(y2, y3);
                }
            }
            // no trailing sync: >=NIT per-iter barriers separate epilogues
        }
        // reset accumulators for next tile
        #pragma unroll
        for (int t = 0; t < 2; t++)
            #pragma unroll
            for (int j = 0; j < 8; j++)
                #pragma unroll
                for (int q = 0; q < 4; q++) acc[t][j][q] = 0.f;
    }
}

// ---------------- launch ----------------
extern "C" void kernel_launch(void* const* d_in, const int* in_sizes, int n_in,
                              void* d_out, int out_size) {
    const float* feat = (const float*)d_in[0];
    const float* W1 = (const float*)d_in[1];  const float* b1 = (const float*)d_in[2];
    const float* g1 = (const float*)d_in[3];  const float* be1 = (const float*)d_in[4];
    const float* a1 = (const float*)d_in[5];
    const float* W2 = (const float*)d_in[6];  const float* b2 = (const float*)d_in[7];
    const float* g2 = (const float*)d_in[8];  const float* be2 = (const float*)d_in[9];
    const float* a2 = (const float*)d_in[10];
    const float* W3 = (const float*)d_in[11]; const float* b3 = (const float*)d_in[12];
    const int* src = (const int*)d_in[13];
    const int* dst = (const int*)d_in[14];
    float* out = (float*)d_out;

    void* p;
    cudaGetSymbolAddress(&p, g_f16);   __half* f16 = (__half*)p;
    cudaGetSymbolAddress(&p, g_a16);   __half* a16 = (__half*)p;
    cudaGetSymbolAddress(&p, g_hh);    __half* hh = (__half*)p;
    cudaGetSymbolAddress(&p, g_p16);   __half* p16 = (__half*)p;
    cudaGetSymbolAddress(&p, g_q16);   __half* q16 = (__half*)p;
    cudaGetSymbolAddress(&p, g_w1);    __half* w1 = (__half*)p;
    cudaGetSymbolAddress(&p, g_w2);    __half* w2 = (__half*)p;
    cudaGetSymbolAddress(&p, g_w3);    __half* w3 = (__half*)p;

    // smem: 4 stages + params(3N) + red(BM*NW*2)
    constexpr int SM1 = 4 * 80 * (64 + 256) + 3 * 256 * 4 + 64 * 4 * 2 * 4;   // 107520
    constexpr int SM3 = 4 * 80 * (128 + 128) + 3 * 128 * 4 + 128 * 2 * 2 * 4; // 85504
    cudaFuncSetAttribute(k_pgemm<128, 64, 256, 1, 1>, cudaFuncAttributeMaxDynamicSharedMemorySize, SM1);
    cudaFuncSetAttribute(k_pgemm<256, 64, 256, 1, 0>, cudaFuncAttributeMaxDynamicSharedMemorySize, SM1);
    cudaFuncSetAttribute(k_pgemm<256, 128, 128, 0, 1>, cudaFuncAttributeMaxDynamicSharedMemorySize, SM3);

    // prep: single persistent kernel with grid barriers
    k_prep<<<PP, 256>>>(src, dst, W1, W2, W3, feat);

    const int NT1 = (NN + 63) / 64;    // 1563
    const int NT3 = (NN + 127) / 128;  // 782

    // layer 1: agg(f16 pre-scaled) -> a16 ; pGEMM 128->256 +LN, out *dno -> hh
    k_agg<128, 1><<<(NN + 7) / 8, 256>>>(f16, a16, nullptr, nullptr);
    k_pgemm<128, 64, 256, 1, 1><<<PG, 256, SM1>>>(a16, w1, b1, g1, be1, a1, hh, NT1);

    // layer 2: agg(hh) -> a16 ; pGEMM 256->256 +LN (unscaled) -> p16
    k_agg<256, 1><<<(NN + 7) / 8, 256>>>(hh, a16, nullptr, nullptr);
    k_pgemm<256, 64, 256, 1, 0><<<PG, 256, SM1>>>(a16, w2, b2, g2, be2, a2, p16, NT1);

    // layer 3: pGEMM 256->128 raw, out *dno -> q16 ; final agg (x+b3)*dni -> out
    k_pgemm<256, 128, 128, 0, 1><<<PG, 256, SM3>>>(p16, w3, nullptr, nullptr,
                                                   nullptr, nullptr, q16, NT3);
    k_agg<128, 2><<<(NN + 7) / 8, 256>>>(q16, nullptr, out, b3);
}

// round 16
// speedup vs baseline: 1.0732x; 1.0732x over previous
#include <cuda_runtime.h>
#include <cuda_fp16.h>
#include <cstdint>

#define NN 100000
#define EE 1600000
#define NSB 98            // ceil(NN/1024)
#define PG 304            // persistent GEMM grid (2 x 152 SMs)
typedef unsigned long long u64;
typedef unsigned int u32;

// ---------------- device scratch ----------------
__device__ __half g_f16[(size_t)NN * 128];    // feat fp16 (pre-scaled by dno)
__device__ __half g_a16[(size_t)NN * 256];    // agg output fp16
__device__ __half g_hh[(size_t)NN * 256];     // L1 out fp16 (pre-scaled by dno)
__device__ __half g_p16[(size_t)NN * 256];    // L2 out fp16 (unscaled)
__device__ __half g_q16[(size_t)NN * 128];    // L3 gemm out fp16 (pre-scaled by dno)
__device__ __half g_w1[256 * 128];
__device__ __half g_w2[256 * 256];
__device__ __half g_w3[128 * 256];
__device__ float g_dno[NN], g_dni[NN];
__device__ int g_cout[NN], g_cin[NN];
__device__ int g_ptr[NN + 1], g_cur[NN], g_csrc[EE];
__device__ int g_part[128];

// ---------------- helpers ----------------
__device__ __forceinline__ void addh8(float* a, const uint4 v) {
    const __half2* h = (const __half2*)&v;
    #pragma unroll
    for (int j = 0; j < 4; j++) {
        float2 f = __half22float2(h[j]);
        a[2 * j] += f.x; a[2 * j + 1] += f.y;
    }
}
__device__ __forceinline__ uint4 hadd4(const uint4 x, const uint4 y) {
    const __half2* hx = (const __half2*)&x;
    const __half2* hy = (const __half2*)&y;
    uint4 r;
    __half2* hr = (__half2*)&r;
    #pragma unroll
    for (int j = 0; j < 4; j++) hr[j] = __hadd2(hx[j], hy[j]);
    return r;
}
__device__ __forceinline__ uint4 pk8(const float* a) {
    __half2 h0 = __floats2half2_rn(a[0], a[1]);
    __half2 h1 = __floats2half2_rn(a[2], a[3]);
    __half2 h2 = __floats2half2_rn(a[4], a[5]);
    __half2 h3 = __floats2half2_rn(a[6], a[7]);
    return make_uint4(*(u32*)&h0, *(u32*)&h1, *(u32*)&h2, *(u32*)&h3);
}
__device__ __forceinline__ void mma16816(float* c, const u32* a, const u32* b) {
    asm volatile(
        "mma.sync.aligned.m16n8k16.row.col.f32.f16.f16.f32 "
        "{%0,%1,%2,%3},{%4,%5,%6,%7},{%8,%9},{%0,%1,%2,%3};"
        : "+f"(c[0]), "+f"(c[1]), "+f"(c[2]), "+f"(c[3])
        : "r"(a[0]), "r"(a[1]), "r"(a[2]), "r"(a[3]), "r"(b[0]), "r"(b[1]));
}
__device__ __forceinline__ void cpa16(void* s, const void* g) {
    u32 sa = (u32)__cvta_generic_to_shared(s);
    asm volatile("cp.async.cg.shared.global [%0], [%1], 16;" :: "r"(sa), "l"(g));
}
__device__ __forceinline__ void ldsm4(u32* r, u32 a) {
    asm volatile("ldmatrix.sync.aligned.m8n8.x4.shared.b16 {%0,%1,%2,%3},[%4];"
                 : "=r"(r[0]), "=r"(r[1]), "=r"(r[2]), "=r"(r[3]) : "r"(a));
}

// ---------------- prep ----------------
__global__ void k_zero() {
    int i = blockIdx.x * blockDim.x + threadIdx.x;
    if (i < (NN + 3) / 4) {
        ((int4*)g_cout)[i] = make_int4(0, 0, 0, 0);
        ((int4*)g_cin)[i] = make_int4(0, 0, 0, 0);
    }
}

// fused: degrees (blocks [0,6250)) + weight transposes ([6250,6762))
__global__ void k_degmisc(const int* __restrict__ src, const int* __restrict__ dst,
                          const float* __restrict__ W1, const float* __restrict__ W2,
                          const float* __restrict__ W3) {
    const int b = blockIdx.x, tid = threadIdx.x;
    if (b < 6250) {
        int i = b * 256 + tid;
        if (i < EE) {
            atomicAdd(&g_cout[src[i]], 1);
            atomicAdd(&g_cin[dst[i]], 1);
        }
    } else {
        int i = (b - 6250) * 256 + tid;   // 0..131071
        if (i < 32768) {
            int n = i / 128, k = i % 128;
            g_w1[i] = __float2half_rn(W1[(size_t)k * 256 + n]);
        } else if (i < 98304) {
            int j = i - 32768;
            int n = j / 256, k = j % 256;
            g_w2[j] = __float2half_rn(W2[(size_t)k * 256 + n]);
        } else {
            int j = i - 98304;
            int n = j / 256, k = j % 256;
            g_w3[j] = __float2half_rn(W3[(size_t)k * 128 + n]);
        }
    }
}

// fused: deg norms (blocks [0,391)) + partial sums ([391,489))
__global__ void k_normpart() {
    const int b = blockIdx.x, tid = threadIdx.x;
    if (b < 391) {
        int i = b * 256 + tid;
        if (i < NN) {
            int co = g_cout[i]; if (co < 1) co = 1;
            int ci = g_cin[i];  if (ci < 1) ci = 1;
            g_dno[i] = rsqrtf((float)co);
            g_dni[i] = rsqrtf((float)ci);
        }
    } else {
        int pb = b - 391;
        int s = 0;
        for (int j = tid; j < 1024; j += 256) {
            int i = pb * 1024 + j;
            s += (i < NN) ? g_cin[i] : 0;
        }
        #pragma unroll
        for (int o = 16; o; o >>= 1) s += __shfl_xor_sync(0xffffffffu, s, o);
        __shared__ int sh[8];
        if ((tid & 31) == 0) sh[tid >> 5] = s;
        __syncthreads();
        if (tid == 0) {
            int t = 0;
            #pragma unroll
            for (int j = 0; j < 8; j++) t += sh[j];
            g_part[pb] = t;
        }
    }
}

// scat with inline prefix over g_part
__global__ void k_scat() {
    __shared__ int ws[32], ws2[32];
    __shared__ int base_s;
    int b = blockIdx.x, tid = threadIdx.x;
    int lane = tid & 31, w = tid >> 5;

    int pv = (tid < b) ? g_part[tid] : 0;
    #pragma unroll
    for (int o = 16; o; o >>= 1) pv += __shfl_xor_sync(0xffffffffu, pv, o);
    if (lane == 0) ws2[w] = pv;
    __syncthreads();
    if (tid == 0) {
        int t = 0;
        #pragma unroll
        for (int j = 0; j < 4; j++) t += ws2[j];
        base_s = t;
    }
    __syncthreads();

    int i = b * 1024 + tid;
    int v = (i < NN) ? g_cin[i] : 0;
    int x = v;
    #pragma unroll
    for (int o = 1; o < 32; o <<= 1) {
        int t = __shfl_up_sync(0xffffffffu, x, o);
        if (lane >= o) x += t;
    }
    if (lane == 31) ws[w] = x;
    __syncthreads();
    if (w == 0) {
        int s = ws[lane];
        #pragma unroll
        for (int o = 1; o < 32; o <<= 1) {
            int t = __shfl_up_sync(0xffffffffu, s, o);
            if (lane >= o) s += t;
        }
        ws[lane] = s;
    }
    __syncthreads();
    int pre = (w > 0) ? ws[w - 1] : 0;
    int exc = base_s + pre + x - v;
    if (i < NN) { g_ptr[i] = exc; g_cur[i] = exc; }
    if (b == 0 && tid == 0) g_ptr[NN] = EE;
}

// fused: CSR fill (blocks [0,6250)) + feat cvt*dno ([6250,18750))
__global__ void k_fillcvt(const int* __restrict__ src, const int* __restrict__ dst,
                          const float* __restrict__ feat) {
    const int b = blockIdx.x, tid = threadIdx.x;
    if (b < 6250) {
        int i = b * 256 + tid;
        if (i < EE) {
            int d = dst[i];
            int p = atomicAdd(&g_cur[d], 1);
            g_csrc[p] = src[i];
        }
    } else {
        int i = (b - 6250) * 256 + tid;   // float4 index, < 3.2M
        if (i < NN * 128 / 4) {
            float4 v = ((const float4*)feat)[i];
            float d = g_dno[i >> 5];      // 32 float4 per row
            __half2 a = __floats2half2_rn(v.x * d, v.y * d);
            __half2 bb = __floats2half2_rn(v.z * d, v.w * d);
            ((uint2*)g_f16)[i] = make_uint2(*(u32*)&a, *(u32*)&bb);
        }
    }
}

// ---------------- aggregation (warp-per-node, CSR, uint4 gathers) ----------------
// D=256: fp16 pairwise (level-1) accumulation to halve fma-pipe convert/add work.
template<int D, int MODE>
__global__ void k_agg(const __half* __restrict__ in,
                      __half* __restrict__ oh, float* __restrict__ of,
                      const float* __restrict__ b3) {
    const int w = (blockIdx.x << 3) + (threadIdx.x >> 5);
    const int lane = threadIdx.x & 31;
    if (w >= NN) return;
    const int beg = g_ptr[w], end = g_ptr[w + 1];
    float a[8] = {0.f, 0.f, 0.f, 0.f, 0.f, 0.f, 0.f, 0.f};

    if (D == 256) {
        int e = beg;
        for (; e + 4 <= end; e += 4) {
            int s0 = g_csrc[e], s1 = g_csrc[e + 1];
            int s2 = g_csrc[e + 2], s3 = g_csrc[e + 3];
            uint4 v0 = ((const uint4*)(in + (size_t)s0 * 256))[lane];
            uint4 v1 = ((const uint4*)(in + (size_t)s1 * 256))[lane];
            uint4 v2 = ((const uint4*)(in + (size_t)s2 * 256))[lane];
            uint4 v3 = ((const uint4*)(in + (size_t)s3 * 256))[lane];
            uint4 p01 = hadd4(v0, v1);
            uint4 p23 = hadd4(v2, v3);
            addh8(a, p01); addh8(a, p23);
        }
        for (; e < end; e++) {
            uint4 v = ((const uint4*)(in + (size_t)g_csrc[e] * 256))[lane];
            addh8(a, v);
        }
        ((uint4*)(oh + (size_t)w * 256))[lane] = pk8(a);
    } else {
        const int slot = lane >> 4;      // which edge of the pair
        const int ch = lane & 15;        // 16B chunk within row
        int e = beg;
        for (; e + 4 <= end; e += 4) {
            int e0 = g_csrc[e + slot], e1 = g_csrc[e + 2 + slot];
            uint4 v0 = ((const uint4*)(in + (size_t)e0 * 128))[ch];
            uint4 v1 = ((const uint4*)(in + (size_t)e1 * 128))[ch];
            addh8(a, v0); addh8(a, v1);
        }
        for (; e < end; e += 2) {
            int ee = e + slot;
            if (ee < end) {
                uint4 v = ((const uint4*)(in + (size_t)g_csrc[ee] * 128))[ch];
                addh8(a, v);
            }
        }
        #pragma unroll
        for (int j = 0; j < 8; j++)
            a[j] += __shfl_xor_sync(0xffffffffu, a[j], 16);
        if (MODE == 1) {
            if (slot == 0)
                ((uint4*)(oh + (size_t)w * 128))[ch] = pk8(a);
        } else {
            if (slot == 0) {
                float4 b0 = ((const float4*)b3)[2 * ch];
                float4 b1 = ((const float4*)b3)[2 * ch + 1];
                float d = g_dni[w];
                float4 o0, o1;
                o0.x = (a[0] + b0.x) * d; o0.y = (a[1] + b0.y) * d;
                o0.z = (a[2] + b0.z) * d; o0.w = (a[3] + b0.w) * d;
                o1.x = (a[4] + b1.x) * d; o1.y = (a[5] + b1.y) * d;
                o1.z = (a[6] + b1.z) * d; o1.w = (a[7] + b1.w) * d;
                ((float4*)(of + (size_t)w * 128))[2 * ch] = o0;
                ((float4*)(of + (size_t)w * 128))[2 * ch + 1] = o1;
            }
        }
    }
}

// ---------------- persistent fp16 GEMM, 4-stage pipeline, 1 sync/iter -----------
// B fragments via paired ldsm4. EPI 0: raw ; 1: bias,deg_in,LN,PReLU. SCO: *dno.
template<int K, int BM, int N, int EPI, int SCO>
__global__ void __launch_bounds__(256, 2)
k_pgemm(const __half* __restrict__ A, const __half* __restrict__ B,
        const float* __restrict__ bias, const float* __restrict__ gam,
        const float* __restrict__ bet, const float* __restrict__ alp,
        __half* __restrict__ Co, int NT) {
    extern __shared__ char smem[];
    constexpr int NW = N / 64;
    constexpr int SA = 80;
    constexpr int STG = SA * (BM + N);
    constexpr int OA = 0;
    constexpr int OB = BM * SA;
    constexpr int NIT = K / 32;
    constexpr int NS = 4;
    constexpr int POFF = NS * STG;
    float* pbias = (float*)(smem + POFF);
    float* pgam  = pbias + N;
    float* pbet  = pgam + N;
    float* red   = pbet + N;          // [BM][NW][2]

    const int tid = threadIdx.x;
    const int wid = tid >> 5, lane = tid & 31;
    const int g = lane >> 2, ti = lane & 3;
    const int mw = wid / NW, nw = wid % NW;
    const int bx = blockIdx.x, G = gridDim.x;
    const u32 smem_u = (u32)__cvta_generic_to_shared(smem);

    const u32 rA = (u32)(((lane & 7) + 8 * ((lane >> 3) & 1)) * SA + 16 * ((lane >> 4) & 1));
    const u32 rB4 = (u32)((((lane >> 4) & 1) * 8 + (lane & 7)) * SA + ((lane >> 3) & 1) * 16);

    if (EPI >= 1) {
        for (int i = tid; i < N; i += 256) {
            pbias[i] = bias[i]; pgam[i] = gam[i]; pbet[i] = bet[i];
        }
    }
    const float alpha = (EPI >= 1) ? __ldg(alp) : 0.f;

    if (bx >= NT) return;
    const int J = (NT - 1 - bx) / G + 1;
    const int total = J * NIT;

    auto issue = [&](int s) {
        const int tile = bx + (s / NIT) * G;
        const int mb = tile * BM;
        const int kb = (s % NIT) * 32;
        char* base = smem + (s % NS) * STG;
        #pragma unroll
        for (int i = tid; i < BM * 4; i += 256) {
            int r = i >> 2, q = i & 3;
            int rg = mb + r; if (rg > NN - 1) rg = NN - 1;
            cpa16(base + OA + r * SA + q * 16, A + (size_t)rg * K + kb + q * 8);
        }
        #pragma unroll
        for (int i = tid; i < N * 4; i += 256) {
            int r = i >> 2, q = i & 3;
            cpa16(base + OB + r * SA + q * 16, B + (size_t)r * K + kb + q * 8);
        }
        asm volatile("cp.async.commit_group;" ::: "memory");
    };

    float acc[2][8][4];
    #pragma unroll
    for (int t = 0; t < 2; t++)
        #pragma unroll
        for (int j = 0; j < 8; j++)
            #pragma unroll
            for (int q = 0; q < 4; q++) acc[t][j][q] = 0.f;

    issue(0);
    if (total > 1) issue(1);

    for (int s = 0; s < total; s++) {
        if (s + 2 < total) {
            issue(s + 2);
            asm volatile("cp.async.wait_group 2;" ::: "memory");
        } else if (s + 1 < total) {
            asm volatile("cp.async.wait_group 1;" ::: "memory");
        } else {
            asm volatile("cp.async.wait_group 0;" ::: "memory");
        }
        __syncthreads();   // single barrier per iteration (4-stage ring is drift-safe)
        const int buf = s % NS;
        const u32 aA = smem_u + buf * STG + OA + (u32)((mw * 32) * SA) + rA;
        const u32 aB = smem_u + buf * STG + OB + (u32)((nw * 64) * SA) + rB4;
        #pragma unroll
        for (int kt = 0; kt < 2; kt++) {
            const u32 kof = kt * 32;
            u32 af[2][4];
            #pragma unroll
            for (int t = 0; t < 2; t++) ldsm4(af[t], aA + (u32)(t * 16 * SA) + kof);
            #pragma unroll
            for (int j2 = 0; j2 < 4; j2++) {
                u32 bf[4];
                ldsm4(bf, aB + (u32)(j2 * 16 * SA) + kof);
                #pragma unroll
                for (int t = 0; t < 2; t++) {
                    mma16816(acc[t][2 * j2 + 0], af[t], bf + 0);
                    mma16816(acc[t][2 * j2 + 1], af[t], bf + 2);
                }
            }
        }

        if ((s % NIT) != NIT - 1) continue;

        // ---- epilogue for tile s/NIT ----
        const int mbase = (bx + (s / NIT) * G) * BM;
        if (EPI == 0) {
            #pragma unroll
            for (int t = 0; t < 2; t++) {
                int rl = mbase + mw * 32 + t * 16 + g;
                int rh = rl + 8;
                float sl = SCO ? g_dno[(rl < NN) ? rl : (NN - 1)] : 1.f;
                float sh = SCO ? g_dno[(rh < NN) ? rh : (NN - 1)] : 1.f;
                #pragma unroll
                for (int j = 0; j < 8; j++) {
                    int c = nw * 64 + j * 8 + ti * 2;
                    if (rl < NN) {
                        __half2 v = __floats2half2_rn(acc[t][j][0] * sl, acc[t][j][1] * sl);
                        *(__half2*)(Co + (size_t)rl * N + c) = v;
                    }
                    if (rh < NN) {
                        __half2 v = __floats2half2_rn(acc[t][j][2] * sh, acc[t][j][3] * sh);
                        *(__half2*)(Co + (size_t)rh * N + c) = v;
                    }
                }
            }
        } else {
            float mul[2], invl[2], muh[2], invh[2];
            #pragma unroll
            for (int t = 0; t < 2; t++) {
                int rloc = mw * 32 + t * 16 + g;
                int rl = mbase + rloc, rh = rl + 8;
                float dl = g_dni[(rl < NN) ? rl : (NN - 1)];
                float dh = g_dni[(rh < NN) ? rh : (NN - 1)];
                float s0 = 0.f, q0 = 0.f, s1 = 0.f, q1 = 0.f;
                #pragma unroll
                for (int j = 0; j < 8; j++) {
                    int c = nw * 64 + j * 8 + ti * 2;
                    float b0 = pbias[c], b1 = pbias[c + 1];
                    float v0 = (acc[t][j][0] + b0) * dl;
                    float v1 = (acc[t][j][1] + b1) * dl;
                    float v2 = (acc[t][j][2] + b0) * dh;
                    float v3 = (acc[t][j][3] + b1) * dh;
                    acc[t][j][0] = v0; acc[t][j][1] = v1;
                    acc[t][j][2] = v2; acc[t][j][3] = v3;
                    s0 += v0 + v1; q0 += v0 * v0 + v1 * v1;
                    s1 += v2 + v3; q1 += v2 * v2 + v3 * v3;
                }
                #pragma unroll
                for (int o = 1; o <= 2; o <<= 1) {
                    s0 += __shfl_xor_sync(0xffffffffu, s0, o);
                    q0 += __shfl_xor_sync(0xffffffffu, q0, o);
                    s1 += __shfl_xor_sync(0xffffffffu, s1, o);
                    q1 += __shfl_xor_sync(0xffffffffu, q1, o);
                }
                if (ti == 0) {
                    red[(rloc * NW + nw) * 2 + 0] = s0;
                    red[(rloc * NW + nw) * 2 + 1] = q0;
                    red[((rloc + 8) * NW + nw) * 2 + 0] = s1;
                    red[((rloc + 8) * NW + nw) * 2 + 1] = q1;
                }
            }
            __syncthreads();
            #pragma unroll
            for (int t = 0; t < 2; t++) {
                int rloc = mw * 32 + t * 16 + g;
                float s0 = 0.f, q0 = 0.f, s1 = 0.f, q1 = 0.f;
                #pragma unroll
                for (int k = 0; k < NW; k++) {
                    s0 += red[(rloc * NW + k) * 2 + 0];
                    q0 += red[(rloc * NW + k) * 2 + 1];
                    s1 += red[((rloc + 8) * NW + k) * 2 + 0];
                    q1 += red[((rloc + 8) * NW + k) * 2 + 1];
                }
                float m0 = s0 * (1.0f / N), m1 = s1 * (1.0f / N);
                mul[t] = m0; muh[t] = m1;
                invl[t] = rsqrtf(q0 * (1.0f / N) - m0 * m0 + 1e-5f);
                invh[t] = rsqrtf(q1 * (1.0f / N) - m1 * m1 + 1e-5f);
            }
            #pragma unroll
            for (int t = 0; t < 2; t++) {
                int rl = mbase + mw * 32 + t * 16 + g;
                int rh = rl + 8;
                float sl = SCO ? g_dno[(rl < NN) ? rl : (NN - 1)] : 1.f;
                float sh = SCO ? g_dno[(rh < NN) ? rh : (NN - 1)] : 1.f;
                #pragma unroll
                for (int j = 0; j < 8; j++) {
                    int c = nw * 64 + j * 8 + ti * 2;
                    float g0 = pgam[c], g1 = pgam[c + 1];
                    float e0 = pbet[c], e1 = pbet[c + 1];
                    float y0 = g0 * (acc[t][j][0] - mul[t]) * invl[t] + e0;
                    float y1 = g1 * (acc[t][j][1] - mul[t]) * invl[t] + e1;
                    float y2 = g0 * (acc[t][j][2] - muh[t]) * invh[t] + e0;
                    float y3 = g1 * (acc[t][j][3] - muh[t]) * invh[t] + e1;
                    y0 = (y0 >= 0.f) ? y0 : alpha * y0;
                    y1 = (y1 >= 0.f) ? y1 : alpha * y1;
                    y2 = (y2 >= 0.f) ? y2 : alpha * y2;
                    y3 = (y3 >= 0.f) ? y3 : alpha * y3;
                    if (SCO) { y0 *= sl; y1 *= sl; y2 *= sh; y3 *= sh; }
                    if (rl < NN)
                        *(__half2*)(Co + (size_t)rl * N + c) = __floats2half2_rn(y0, y1);
                    if (rh < NN)
                        *(__half2*)(Co + (size_t)rh * N + c) = __floats2half2_rn(y2, y3);
                }
            }
            // no trailing sync: >=NIT per-iter barriers separate epilogues
        }
        // reset accumulators for next tile
        #pragma unroll
        for (int t = 0; t < 2; t++)
            #pragma unroll
            for (int j = 0; j < 8; j++)
                #pragma unroll
                for (int q = 0; q < 4; q++) acc[t][j][q] = 0.f;
    }
}

// ---------------- launch ----------------
extern "C" void kernel_launch(void* const* d_in, const int* in_sizes, int n_in,
                              void* d_out, int out_size) {
    const float* feat = (const float*)d_in[0];
    const float* W1 = (const float*)d_in[1];  const float* b1 = (const float*)d_in[2];
    const float* g1 = (const float*)d_in[3];  const float* be1 = (const float*)d_in[4];
    const float* a1 = (const float*)d_in[5];
    const float* W2 = (const float*)d_in[6];  const float* b2 = (const float*)d_in[7];
    const float* g2 = (const float*)d_in[8];  const float* be2 = (const float*)d_in[9];
    const float* a2 = (const float*)d_in[10];
    const float* W3 = (const float*)d_in[11]; const float* b3 = (const float*)d_in[12];
    const int* src = (const int*)d_in[13];
    const int* dst = (const int*)d_in[14];
    float* out = (float*)d_out;

    void* p;
    cudaGetSymbolAddress(&p, g_f16);   __half* f16 = (__half*)p;
    cudaGetSymbolAddress(&p, g_a16);   __half* a16 = (__half*)p;
    cudaGetSymbolAddress(&p, g_hh);    __half* hh = (__half*)p;
    cudaGetSymbolAddress(&p, g_p16);   __half* p16 = (__half*)p;
    cudaGetSymbolAddress(&p, g_q16);   __half* q16 = (__half*)p;
    cudaGetSymbolAddress(&p, g_w1);    __half* w1 = (__half*)p;
    cudaGetSymbolAddress(&p, g_w2);    __half* w2 = (__half*)p;
    cudaGetSymbolAddress(&p, g_w3);    __half* w3 = (__half*)p;

    // smem: 4 stages + params(3N) + red(BM*NW*2)
    constexpr int SM1 = 4 * 80 * (64 + 256) + 3 * 256 * 4 + 64 * 4 * 2 * 4;   // 107520
    constexpr int SM3 = 4 * 80 * (128 + 128) + 3 * 128 * 4 + 128 * 2 * 2 * 4; // 85504
    cudaFuncSetAttribute(k_pgemm<128, 64, 256, 1, 1>, cudaFuncAttributeMaxDynamicSharedMemorySize, SM1);
    cudaFuncSetAttribute(k_pgemm<256, 64, 256, 1, 0>, cudaFuncAttributeMaxDynamicSharedMemorySize, SM1);
    cudaFuncSetAttribute(k_pgemm<256, 128, 128, 0, 1>, cudaFuncAttributeMaxDynamicSharedMemorySize, SM3);

    // prep (R14 chain — separate kernels; persistent-prep barriers regressed)
    k_zero<<<(NN / 4 + 255) / 256, 256>>>();
    k_degmisc<<<6762, 256>>>(src, dst, W1, W2, W3);
    k_normpart<<<489, 256>>>();
    k_scat<<<NSB, 1024>>>();
    k_fillcvt<<<18750, 256>>>(src, dst, feat);

    const int NT1 = (NN + 63) / 64;    // 1563
    const int NT3 = (NN + 127) / 128;  // 782

    // layer 1: agg(f16 pre-scaled) -> a16 ; pGEMM 128->256 +LN, out *dno -> hh
    k_agg<128, 1><<<(NN + 7) / 8, 256>>>(f16, a16, nullptr, nullptr);
    k_pgemm<128, 64, 256, 1, 1><<<PG, 256, SM1>>>(a16, w1, b1, g1, be1, a1, hh, NT1);

    // layer 2: agg(hh) -> a16 ; pGEMM 256->256 +LN (unscaled) -> p16
    k_agg<256, 1><<<(NN + 7) / 8, 256>>>(hh, a16, nullptr, nullptr);
    k_pgemm<256, 64, 256, 1, 0><<<PG, 256, SM1>>>(a16, w2, b2, g2, be2, a2, p16, NT1);

    // layer 3: pGEMM 256->128 raw, out *dno -> q16 ; final agg (x+b3)*dni -> out
    k_pgemm<256, 128, 128, 0, 1><<<PG, 256, SM3>>>(p16, w3, nullptr, nullptr,
                                                   nullptr, nullptr, q16, NT3);
    k_agg<128, 2><<<(NN + 7) / 8, 256>>>(q16, nullptr, out, b3);
}